// round 5
// baseline (speedup 1.0000x reference)
#include <cuda_runtime.h>

typedef unsigned long long ull;

#define NROWS   16384
#define DIMP    1024
#define NCLS    10
#define IMG     784
#define QSTRIDE 21              // ull per d-quad group in smem: 20 data + 1 pad (168 B)

// Packed reference pairs (prologue output), dense layout:
// g_refp[(d>>2)*20 + p*4 + (d&3)] = ( ref[2p][d], ref[2p+1][d] )
__device__ ull g_refp[256 * 20];

// ---------- f32x2 helpers ----------
__device__ __forceinline__ ull pack2(float lo, float hi) {
    ull r;
    asm("mov.b64 %0, {%1, %2};" : "=l"(r) : "f"(lo), "f"(hi));
    return r;
}
__device__ __forceinline__ void unpack2(ull v, float& lo, float& hi) {
    asm("mov.b64 {%0, %1}, %2;" : "=f"(lo), "=f"(hi) : "l"(v));
}
__device__ __forceinline__ void fma2(ull& acc, ull a, ull b) {
    asm("fma.rn.f32x2 %0, %1, %2, %0;" : "+l"(acc) : "l"(a), "l"(b));
}
__device__ __forceinline__ void add2(ull& acc, ull a) {
    asm("add.rn.f32x2 %0, %1, %0;" : "+l"(acc) : "l"(a));
}

#define COMP(v, j) ((j) == 0 ? (v).x : ((j) == 1 ? (v).y : ((j) == 2 ? (v).z : (v).w)))

// ---------- prologue: block p normalizes classes 2p, 2p+1 and writes packed pairs ----------
__global__ void ref_pack_kernel(const float* __restrict__ canon) {
    __shared__ float v0[DIMP], v1[DIMP];
    __shared__ float wred[16];
    __shared__ float invs[2];
    const int p = blockIdx.x, t = threadIdx.x;
    const float* c0 = canon + (2 * p) * IMG;
    const float* c1 = canon + (2 * p + 1) * IMG;
    float s0 = 0.f, s1 = 0.f;
    for (int i = t; i < DIMP; i += 256) {
        float a = (i < IMG) ? c0[i] : 0.f;
        float b = (i < IMG) ? c1[i] : 0.f;
        v0[i] = a; v1[i] = b;
        s0 += a * a; s1 += b * b;
    }
    #pragma unroll
    for (int o = 16; o; o >>= 1) {
        s0 += __shfl_xor_sync(0xFFFFFFFFu, s0, o);
        s1 += __shfl_xor_sync(0xFFFFFFFFu, s1, o);
    }
    if ((t & 31) == 0) { wred[t >> 5] = s0; wred[8 + (t >> 5)] = s1; }
    __syncthreads();
    if (t == 0) {
        float a = 0.f, b = 0.f;
        #pragma unroll
        for (int i = 0; i < 8; i++) { a += wred[i]; b += wred[8 + i]; }
        invs[0] = 1.0f / sqrtf(a);
        invs[1] = 1.0f / sqrtf(b);
    }
    __syncthreads();
    const float i0 = invs[0], i1 = invs[1];
    for (int d = t; d < DIMP; d += 256)
        g_refp[(d >> 2) * 20 + p * 4 + (d & 3)] = pack2(v0[d] * i0, v1[d] * i1);
}

// ---------- main kernel ----------
// 256 threads = 8 warps, 2 rows per warp -> 16 rows/block, grid = 1024.
// acc A[p*4 + arr*2 + row] packs (class 2p, class 2p+1) partial sums.
// Depth-2 register prefetch: LDGs for tile k+2 issue at top of body k.
__global__ __launch_bounds__(256, 2) void swap_test_kernel(
    const float* __restrict__ zre, const float* __restrict__ zim,
    float* __restrict__ out) {

    __shared__ __align__(16) ull sm[256 * QSTRIDE];   // 43008 B

    const int tid = threadIdx.x;

    // stage packed ref into smem: 20 data ull + 1 pad ull per quad group
    for (int i = tid; i < 5120; i += 256) {
        const int q = i / 20;
        const int r = i - q * 20;
        sm[q * QSTRIDE + r] = g_refp[i];
    }
    __syncthreads();

    const int lane = tid & 31;
    const int w    = tid >> 5;
    const size_t rowBase = (size_t)blockIdx.x * 16 + (size_t)w * 2;
    const float4* zr = (const float4*)zre + rowBase * 256;
    const float4* zi = (const float4*)zim + rowBase * 256;
    const char* rp = (const char*)sm + (size_t)lane * (QSTRIDE * 8);

    ull A[20];
    #pragma unroll
    for (int i = 0; i < 20; i++) A[i] = 0ull;

    // tiles: c = current (k), n = k+1, m = k+2 (loaded inside body)
    float4 c0 = zr[lane],      c1 = zr[256 + lane];
    float4 c2 = zi[lane],      c3 = zi[256 + lane];
    float4 n0 = zr[32 + lane], n1 = zr[288 + lane];
    float4 n2 = zi[32 + lane], n3 = zi[288 + lane];

    #pragma unroll
    for (int k = 0; k < 8; k++) {
        float4 m0, m1, m2, m3;
        if (k < 6) {
            const int di = (k + 2) * 32 + lane;
            m0 = zr[di]; m1 = zr[256 + di];
            m2 = zi[di]; m3 = zi[256 + di];
        }

        const char* rk = rp + k * (32 * QSTRIDE * 8);

        #pragma unroll
        for (int j = 0; j < 4; j++) {           // vector component
            const ull dre0 = pack2(COMP(c0, j), COMP(c0, j));
            const ull dre1 = pack2(COMP(c1, j), COMP(c1, j));
            const ull dim0 = pack2(COMP(c2, j), COMP(c2, j));
            const ull dim1 = pack2(COMP(c3, j), COMP(c3, j));
            #pragma unroll
            for (int p = 0; p < 5; p++) {       // class pair
                const ull f = *(const ull*)(rk + p * 32 + j * 8);
                fma2(A[p * 4 + 0], dre0, f);
                fma2(A[p * 4 + 1], dim0, f);
                fma2(A[p * 4 + 2], dre1, f);
                fma2(A[p * 4 + 3], dim1, f);
            }
        }

        c0 = n0; c1 = n1; c2 = n2; c3 = n3;
        if (k < 6) { n0 = m0; n1 = m1; n2 = m2; n3 = m3; }
    }

    __syncthreads();   // all warps done with staged ref -> overlay reduction buffer

    // lane partials: 8 warps x 20 ull rows, stride 33 (conflict-free STS.64)
    ull* red = sm;
    #pragma unroll
    for (int i = 0; i < 20; i++)
        red[(w * 20 + i) * 33 + lane] = A[i];
    __syncthreads();

    // 80 tasks: (warp w2, class-pair p, row j) -> 2 outputs each
    if (tid < 80) {
        const int w2 = tid / 10;
        const int q  = tid % 10;
        const int p  = q >> 1;
        const int j  = q & 1;
        const int mRe = w2 * 20 + p * 4 + j * 2;
        ull sre = 0ull, sim = 0ull;
        #pragma unroll
        for (int x = 0; x < 32; x++) {
            add2(sre, red[mRe * 33 + x]);
            add2(sim, red[(mRe + 1) * 33 + x]);
        }
        float reL, reH, imL, imH;
        unpack2(sre, reL, reH);
        unpack2(sim, imL, imH);
        const size_t row = (size_t)blockIdx.x * 16 + (size_t)w2 * 2 + (size_t)j;
        out[row * NCLS + 2 * p]     = reL * reL + imL * imL;
        out[row * NCLS + 2 * p + 1] = reH * reH + imH * imH;
    }
}

extern "C" void kernel_launch(void* const* d_in, const int* in_sizes, int n_in,
                              void* d_out, int out_size) {
    const float* zre   = (const float*)d_in[0];
    const float* zim   = (const float*)d_in[1];
    const float* canon = (const float*)d_in[2];
    float* out = (float*)d_out;

    ref_pack_kernel<<<NCLS / 2, 256>>>(canon);
    swap_test_kernel<<<NROWS / 16, 256>>>(zre, zim, out);
}